// round 14
// baseline (speedup 1.0000x reference)
#include <cuda_runtime.h>
#include <math.h>
#include <stdint.h>

#define B   64
#define T   512
#define F   64
#define H   256
#define G   (3*H)   /* 768 */
#define D   64

#define CLU 4         /* CTAs per cluster */
#define KS  (H/CLU)   /* 64 rows / hidden units per CTA */
#define NB  2         /* batches per cluster */
#define TPB 512       /* 2 threads per gate column (k-split halves) */
#define NSRC (CLU*2)  /* 8 partial sources: (CTA rank, half) */
#define RSTRIDE 196   /* Rt2 row stride in floats: 196%32==4 -> conflict-free */

typedef unsigned long long ull;

__device__ float g_xproj[B * T * G];

// ---------------------------------------------------------------------------
// PTX helpers (all proven in the 923us run)
// ---------------------------------------------------------------------------
__device__ __forceinline__ uint32_t smem_u32(const void* p) {
    return (uint32_t)__cvta_generic_to_shared(p);
}
__device__ __forceinline__ uint32_t mapa_cluster(uint32_t addr, uint32_t rank) {
    uint32_t r;
    asm("mapa.shared::cluster.u32 %0, %1, %2;" : "=r"(r) : "r"(addr), "r"(rank));
    return r;
}
__device__ __forceinline__ void cluster_sync() {
    asm volatile("barrier.cluster.arrive.aligned;" ::: "memory");
    asm volatile("barrier.cluster.wait.aligned;"   ::: "memory");
}
__device__ __forceinline__ uint32_t ctarank() {
    uint32_t r;
    asm("mov.u32 %0, %%cluster_ctarank;" : "=r"(r));
    return r;
}
__device__ __forceinline__ void mbar_init(uint32_t addr, uint32_t cnt) {
    asm volatile("mbarrier.init.shared.b64 [%0], %1;" :: "r"(addr), "r"(cnt) : "memory");
}
__device__ __forceinline__ void mbar_expect_tx(uint32_t addr, uint32_t bytes) {
    asm volatile("mbarrier.arrive.expect_tx.shared.b64 _, [%0], %1;"
                 :: "r"(addr), "r"(bytes) : "memory");
}
__device__ __forceinline__ void mbar_wait(uint32_t addr, uint32_t parity) {
    asm volatile(
        "{\n\t"
        ".reg .pred P;\n"
        "WL_%=:\n\t"
        "mbarrier.try_wait.parity.acquire.cluster.shared::cta.b64 P, [%0], %1;\n\t"
        "@P bra WD_%=;\n\t"
        "bra WL_%=;\n"
        "WD_%=:\n\t"
        "}"
        :: "r"(addr), "r"(parity) : "memory");
}
__device__ __forceinline__ void st_async_f32(uint32_t addr, float v, uint32_t mbar) {
    asm volatile("st.async.shared::cluster.mbarrier::complete_tx::bytes.f32 [%0], %1, [%2];"
                 :: "r"(addr), "f"(v), "r"(mbar) : "memory");
}
__device__ __forceinline__ void lds_v2b64(ull& a, ull& b, uint32_t addr) {
    asm volatile("ld.shared.v2.b64 {%0, %1}, [%2];" : "=l"(a), "=l"(b) : "r"(addr));
}
__device__ __forceinline__ ull ffma2(ull a, ull b, ull c) {
    ull d;
    asm("fma.rn.f32x2 %0, %1, %2, %3;" : "=l"(d) : "l"(a), "l"(b), "l"(c));
    return d;
}
__device__ __forceinline__ ull pack2(float lo, float hi) {
    ull r;
    asm("mov.b64 %0, {%1, %2};" : "=l"(r) : "f"(lo), "f"(hi));
    return r;
}
__device__ __forceinline__ float red2(ull a) {
    float lo, hi;
    asm("mov.b64 {%0, %1}, %2;" : "=f"(lo), "=f"(hi) : "l"(a));
    return lo + hi;
}
__device__ __forceinline__ float sigmoid_f(float x) {
    return __fdividef(1.0f, 1.0f + __expf(-x));
}
__device__ __forceinline__ float tanh_f(float x) {
    const float e = __expf(2.0f * x);
    return 1.0f - __fdividef(2.0f, e + 1.0f);
}

// ---------------------------------------------------------------------------
// Kernel A: xproj = x @ kernel + bias  (EXACT proven 134us version)
// ---------------------------------------------------------------------------
#define XP_ROWS 16
__global__ void __launch_bounds__(768) xproj_kernel(
    const float* __restrict__ x, const float* __restrict__ w,
    const float* __restrict__ bias)
{
    __shared__ __align__(16) float xs[XP_ROWS * F];   // 4 KB
    const int col  = threadIdx.x;
    const int row0 = blockIdx.x * XP_ROWS;

    const float4* xin = (const float4*)(x + (size_t)row0 * F);
    for (int i = threadIdx.x; i < XP_ROWS * F / 4; i += blockDim.x)
        ((float4*)xs)[i] = xin[i];
    __syncthreads();

    ull acc2[XP_ROWS];
#pragma unroll
    for (int r = 0; r < XP_ROWS; r++) acc2[r] = 0ULL;

    const uint32_t xs_a = smem_u32(xs);

#pragma unroll 4
    for (int k4 = 0; k4 < F / 4; k4++) {
        const int k = 4 * k4;
        const float w0 = w[(k + 0) * G + col];
        const float w1 = w[(k + 1) * G + col];
        const float w2 = w[(k + 2) * G + col];
        const float w3 = w[(k + 3) * G + col];
        const ull wp0 = pack2(w0, w1);
        const ull wp1 = pack2(w2, w3);
#pragma unroll
        for (int r = 0; r < XP_ROWS; r++) {
            ull x01, x23;
            lds_v2b64(x01, x23, xs_a + (uint32_t)(r * F + k) * 4u);
            acc2[r] = ffma2(x01, wp0, acc2[r]);
            acc2[r] = ffma2(x23, wp1, acc2[r]);
        }
    }

    const float bv = bias[col];
#pragma unroll
    for (int r = 0; r < XP_ROWS; r++)
        g_xproj[(size_t)(row0 + r) * G + col] = bv + red2(acc2[r]);
}

// ---------------------------------------------------------------------------
// Kernel B: GRU scan. Proven R10 protocol, but 512 threads: thread (j, half)
// computes the half dot-product k in [half*32, half*32+32) for gate columns
// j, H+j, 2H+j. Partials exchanged from 8 sources = (rank, half).
// R packed per-column: Rt2[j*RSTRIDE + gate*64 + k]  (z|r|h contiguous).
// smem (floats): Rt2 50176 | Hs 128 | Ps 2*3072 | mbar
// ---------------------------------------------------------------------------
#define RT2_FLOATS  (H * RSTRIDE)              /* 50176 */
#define HS_OFF      RT2_FLOATS
#define PS_OFF      (HS_OFF + NB * KS)         /* 50304 */
#define PBUF_FLOATS (NSRC * NB * 3 * KS)       /* 3072  */
#define MB_OFF      (PS_OFF + 2 * PBUF_FLOATS) /* 56448 */
#define SMEM_BYTES  (MB_OFF * 4 + 16)          /* 225808 */
#define RX_BYTES    (PBUF_FLOATS * 4)          /* 12288 per step */

__global__ void __launch_bounds__(TPB, 1) __cluster_dims__(CLU, 1, 1)
scan_kernel(const float* __restrict__ R, float* __restrict__ out)
{
    extern __shared__ float smem[];
    float* Rt2 = smem;
    float* Hs  = smem + HS_OFF;
    float* Ps  = smem + PS_OFF;

    const int      tid  = threadIdx.x;        // 0..511
    const uint32_t rank = ctarank();
    const int      cl   = blockIdx.x / CLU;
    const int      b0g  = cl * NB;

    const int j    = tid & 255;               // gate column unit
    const int half = tid >> 8;                // k-half: 0 or 1

    const uint32_t mb_local = smem_u32(smem + MB_OFF);
    if (tid == 0) {
        mbar_init(mb_local,     1);
        mbar_init(mb_local + 8, 1);
    }

    // load own 64-row slice of R into per-column packed layout:
    // Rt2[col*RSTRIDE + gate*64 + k] = R[(rank*KS+k)*G + gate*H + col]
    {
        const float* src = R + (size_t)rank * KS * G;
        for (int i = tid; i < KS * G; i += TPB) {
            const int k   = i / G;
            const int col = i - k * G;           // 0..767 (coalesced gmem)
            const int gt  = col >> 8;            // gate block 0..2
            const int cc  = col & 255;           // unit 0..255
            Rt2[cc * RSTRIDE + gt * KS + k] = src[i];
        }
    }
    if (tid < NB * KS) Hs[tid] = 0.0f;
    __syncthreads();
    cluster_sync();   // mbarriers + Rt2 ready cluster-wide before any st.async

    // exchange constants: source id = (rank, half); dst owns unit j
    const int dstRank = j >> 6;
    const int u64     = j & 63;
    const int src8    = (int)rank * 2 + half;
    const uint32_t ps_local  = smem_u32(Ps);
    // layout [buf][src8][b][g][u]
    const uint32_t slot_off  = (uint32_t)(((src8 * NB) * 3) * KS + u64) * 4u;
    const uint32_t rem_base0 = mapa_cluster(ps_local + slot_off, (uint32_t)dstRank);
    const uint32_t rem_mb    = mapa_cluster(mb_local, (uint32_t)dstRank);
    const uint32_t BUF_B  = (uint32_t)PBUF_FLOATS * 4u;  // 12288
    const uint32_t BAT_B  = (uint32_t)(3 * KS) * 4u;     // 768
    const uint32_t GATE_B = (uint32_t)KS * 4u;           // 256

    // GEMV addresses: this thread's k-window [half*32, half*32+32)
    const uint32_t wz_a = smem_u32(Rt2) + (uint32_t)j * (RSTRIDE * 4u)
                                        + (uint32_t)half * 128u;
    const uint32_t wr_a = wz_a + (uint32_t)KS * 4u;       // +256B: r block
    const uint32_t wh_a = wz_a + (uint32_t)(2 * KS) * 4u; // +512B: h block
    const uint32_t h0_a = smem_u32(Hs) + (uint32_t)half * 128u;
    const uint32_t h1_a = smem_u32(Hs) + (uint32_t)KS * 4u + (uint32_t)half * 128u;

    // gate-thread constants (tid < 128)
    const int gb  = tid >> 6;
    const int gu  = tid & 63;
    const int guu = (int)rank * KS + gu;
    const float* xp_gate  = g_xproj + ((size_t)(b0g + gb) * T) * G + guu;
    float*       out_gate = out     + ((size_t)(b0g + gb) * T) * H + guu;

    for (int t = 0; t < T; t++) {
        const int      bi  = t & 1;
        const uint32_t par = (uint32_t)((t >> 1) & 1);

        if (tid == 0) mbar_expect_tx(mb_local + bi * 8, RX_BYTES);

        // prefetch xproj gate inputs (hide GMEM latency under gemv)
        float xz = 0.f, xr = 0.f, xh = 0.f;
        if (tid < NB * KS) {
            const float* xp = xp_gate + (size_t)t * G;
            xz = __ldg(xp); xr = __ldg(xp + H); xh = __ldg(xp + 2 * H);
        }

        // half GEMV: 8 k4-iterations over this thread's 32-k window
        ull a00 = 0ULL, a01 = 0ULL, a02 = 0ULL;
        ull a10 = 0ULL, a11 = 0ULL, a12 = 0ULL;
#pragma unroll
        for (int k4 = 0; k4 < KS / 8; k4++) {
            const uint32_t o = (uint32_t)k4 * 16u;
            ull wa0, wa1, wb0, wb1, wc0, wc1, p0, p1, q0, q1;
            lds_v2b64(wa0, wa1, wz_a + o);
            lds_v2b64(wb0, wb1, wr_a + o);
            lds_v2b64(wc0, wc1, wh_a + o);
            lds_v2b64(p0,  p1,  h0_a + o);
            lds_v2b64(q0,  q1,  h1_a + o);
            a00 = ffma2(p0, wa0, a00);  a00 = ffma2(p1, wa1, a00);
            a01 = ffma2(p0, wb0, a01);  a01 = ffma2(p1, wb1, a01);
            a02 = ffma2(p0, wc0, a02);  a02 = ffma2(p1, wc1, a02);
            a10 = ffma2(q0, wa0, a10);  a10 = ffma2(q1, wa1, a10);
            a11 = ffma2(q0, wb0, a11);  a11 = ffma2(q1, wb1, a11);
            a12 = ffma2(q0, wc0, a12);  a12 = ffma2(q1, wc1, a12);
        }

        // scatter half-partials to owner CTA (counts tx on owner's barrier)
        {
            const uint32_t base = rem_base0 + (uint32_t)bi * BUF_B;
            const uint32_t mbr  = rem_mb + (uint32_t)bi * 8u;
            st_async_f32(base,                       red2(a00), mbr);
            st_async_f32(base + GATE_B,              red2(a01), mbr);
            st_async_f32(base + 2u * GATE_B,         red2(a02), mbr);
            st_async_f32(base + BAT_B,               red2(a10), mbr);
            st_async_f32(base + BAT_B + GATE_B,      red2(a11), mbr);
            st_async_f32(base + BAT_B + 2u * GATE_B, red2(a12), mbr);
        }

        // gates: wait for all 8 sources' partials, update own units
        if (tid < NB * KS) {
            mbar_wait(mb_local + bi * 8, par);
            const float* pb = Ps + bi * PBUF_FLOATS;
            float sz = 0.f, sr = 0.f, sh = 0.f;
#pragma unroll
            for (int s = 0; s < NSRC; s++) {
                const float* qq = pb + (s * NB + gb) * (3 * KS) + gu;
                sz += qq[0]; sr += qq[KS]; sh += qq[2 * KS];
            }
            const float z  = sigmoid_f(xz + sz);
            const float r  = sigmoid_f(xr + sr);
            const float hh = tanh_f(xh + r * sh);
            const float hn = z * Hs[tid] + (1.0f - z) * hh;
            Hs[tid] = hn;
            out_gate[(size_t)t * H] = hn;
        }
        __syncthreads();   // Hs update visible before next gemv
    }

    cluster_sync();   // keep CTAs alive until all peer traffic drained
}

// ---------------------------------------------------------------------------
// Kernel C: state = tanh(h_last @ dense_w + dense_b)
// ---------------------------------------------------------------------------
__global__ void __launch_bounds__(D) dense_kernel(
    const float* __restrict__ out, const float* __restrict__ w,
    const float* __restrict__ bias, float* __restrict__ state)
{
    const int b = blockIdx.x;
    const int d = threadIdx.x;
    const float* hl = out + ((size_t)b * T + (T - 1)) * H;
    float acc = bias[d];
#pragma unroll 4
    for (int k = 0; k < H; k++)
        acc += hl[k] * w[k * D + d];
    state[(size_t)b * D + d] = tanhf(acc);
}

// ---------------------------------------------------------------------------
extern "C" void kernel_launch(void* const* d_in, const int* in_sizes, int n_in,
                              void* d_out, int out_size)
{
    const float* x     = (const float*)d_in[0];
    const float* kern  = (const float*)d_in[1];
    const float* rkern = (const float*)d_in[2];
    const float* bias  = (const float*)d_in[3];
    const float* dw    = (const float*)d_in[4];
    const float* db    = (const float*)d_in[5];

    float* out   = (float*)d_out;
    float* state = out + (size_t)B * T * H;

    cudaFuncSetAttribute(scan_kernel,
                         cudaFuncAttributeMaxDynamicSharedMemorySize, SMEM_BYTES);

    xproj_kernel<<<(B * T) / XP_ROWS, 768>>>(x, kern, bias);
    scan_kernel<<<(B / NB) * CLU, TPB, SMEM_BYTES>>>(rkern, out);
    dense_kernel<<<B, D>>>(out, dw, db, state);
}

// round 16
// speedup vs baseline: 1.1452x; 1.1452x over previous
#include <cuda_runtime.h>
#include <math.h>
#include <stdint.h>

#define B   64
#define T   512
#define F   64
#define H   256
#define G   (3*H)   /* 768 */
#define D   64

#define CLU 4        /* CTAs per cluster */
#define KS  (H/CLU)  /* 64 rows / hidden units per CTA */
#define NB  2        /* batches per cluster */
#define TPB 256
#define PAD 68       /* Rt row stride: 272B, 16B-aligned, conflict-free */

typedef unsigned long long ull;

__device__ float g_xproj[B * T * G];

// ---------------------------------------------------------------------------
// PTX helpers (proven in the 923us run)
// ---------------------------------------------------------------------------
__device__ __forceinline__ uint32_t smem_u32(const void* p) {
    return (uint32_t)__cvta_generic_to_shared(p);
}
__device__ __forceinline__ uint32_t mapa_cluster(uint32_t addr, uint32_t rank) {
    uint32_t r;
    asm("mapa.shared::cluster.u32 %0, %1, %2;" : "=r"(r) : "r"(addr), "r"(rank));
    return r;
}
__device__ __forceinline__ void cluster_sync() {
    asm volatile("barrier.cluster.arrive.aligned;" ::: "memory");
    asm volatile("barrier.cluster.wait.aligned;"   ::: "memory");
}
__device__ __forceinline__ uint32_t ctarank() {
    uint32_t r;
    asm("mov.u32 %0, %%cluster_ctarank;" : "=r"(r));
    return r;
}
__device__ __forceinline__ void mbar_init(uint32_t addr, uint32_t cnt) {
    asm volatile("mbarrier.init.shared.b64 [%0], %1;" :: "r"(addr), "r"(cnt) : "memory");
}
__device__ __forceinline__ void mbar_expect_tx(uint32_t addr, uint32_t bytes) {
    asm volatile("mbarrier.arrive.expect_tx.shared.b64 _, [%0], %1;"
                 :: "r"(addr), "r"(bytes) : "memory");
}
__device__ __forceinline__ void mbar_wait(uint32_t addr, uint32_t parity) {
    asm volatile(
        "{\n\t"
        ".reg .pred P;\n"
        "WL_%=:\n\t"
        "mbarrier.try_wait.parity.acquire.cluster.shared::cta.b64 P, [%0], %1;\n\t"
        "@P bra WD_%=;\n\t"
        "bra WL_%=;\n"
        "WD_%=:\n\t"
        "}"
        :: "r"(addr), "r"(parity) : "memory");
}
__device__ __forceinline__ void st_async_f32(uint32_t addr, float v, uint32_t mbar) {
    asm volatile("st.async.shared::cluster.mbarrier::complete_tx::bytes.f32 [%0], %1, [%2];"
                 :: "r"(addr), "f"(v), "r"(mbar) : "memory");
}
__device__ __forceinline__ void lds_v2b64(ull& a, ull& b, uint32_t addr) {
    asm volatile("ld.shared.v2.b64 {%0, %1}, [%2];" : "=l"(a), "=l"(b) : "r"(addr));
}
__device__ __forceinline__ ull ffma2(ull a, ull b, ull c) {
    ull d;
    asm("fma.rn.f32x2 %0, %1, %2, %3;" : "=l"(d) : "l"(a), "l"(b), "l"(c));
    return d;
}
__device__ __forceinline__ ull pack2(float lo, float hi) {
    ull r;
    asm("mov.b64 %0, {%1, %2};" : "=l"(r) : "f"(lo), "f"(hi));
    return r;
}
__device__ __forceinline__ float red2(ull a) {
    float lo, hi;
    asm("mov.b64 {%0, %1}, %2;" : "=f"(lo), "=f"(hi) : "l"(a));
    return lo + hi;
}
__device__ __forceinline__ float sigmoid_f(float x) {
    return __fdividef(1.0f, 1.0f + __expf(-x));
}
__device__ __forceinline__ float tanh_f(float x) {
    const float e = __expf(2.0f * x);
    return 1.0f - __fdividef(2.0f, e + 1.0f);
}

// ---------------------------------------------------------------------------
// Kernel A: xproj = x @ kernel + bias. TPB=384, 2 columns per thread:
// each broadcast x LDS feeds 4 FFMA2 -> LDS/issue traffic halved vs 1-col.
// ~95 regs (limit 170 at 384 threads) -> no spill.
// ---------------------------------------------------------------------------
#define XP_ROWS 16
#define XP_TPB  384
__global__ void __launch_bounds__(XP_TPB) xproj_kernel(
    const float* __restrict__ x, const float* __restrict__ w,
    const float* __restrict__ bias)
{
    __shared__ __align__(16) float xs[XP_ROWS * F];   // 4 KB
    const int col0 = threadIdx.x;          // 0..383
    const int col1 = col0 + XP_TPB;        // 384..767
    const int row0 = blockIdx.x * XP_ROWS;

    const float4* xin = (const float4*)(x + (size_t)row0 * F);
    for (int i = threadIdx.x; i < XP_ROWS * F / 4; i += XP_TPB)
        ((float4*)xs)[i] = xin[i];
    __syncthreads();

    ull accA[XP_ROWS], accB[XP_ROWS];
#pragma unroll
    for (int r = 0; r < XP_ROWS; r++) { accA[r] = 0ULL; accB[r] = 0ULL; }

    const uint32_t xs_a = smem_u32(xs);

#pragma unroll 4
    for (int k4 = 0; k4 < F / 4; k4++) {
        const int k = 4 * k4;
        const ull wa0 = pack2(w[(k + 0) * G + col0], w[(k + 1) * G + col0]);
        const ull wa1 = pack2(w[(k + 2) * G + col0], w[(k + 3) * G + col0]);
        const ull wb0 = pack2(w[(k + 0) * G + col1], w[(k + 1) * G + col1]);
        const ull wb1 = pack2(w[(k + 2) * G + col1], w[(k + 3) * G + col1]);
#pragma unroll
        for (int r = 0; r < XP_ROWS; r++) {
            ull x01, x23;
            lds_v2b64(x01, x23, xs_a + (uint32_t)(r * F + k) * 4u);
            accA[r] = ffma2(x01, wa0, accA[r]);
            accA[r] = ffma2(x23, wa1, accA[r]);
            accB[r] = ffma2(x01, wb0, accB[r]);
            accB[r] = ffma2(x23, wb1, accB[r]);
        }
    }

    const float bv0 = bias[col0];
    const float bv1 = bias[col1];
#pragma unroll
    for (int r = 0; r < XP_ROWS; r++) {
        g_xproj[(size_t)(row0 + r) * G + col0] = bv0 + red2(accA[r]);
        g_xproj[(size_t)(row0 + r) * G + col1] = bv1 + red2(accB[r]);
    }
}

// ---------------------------------------------------------------------------
// Kernel B: GRU scan — EXACT proven 923us version (all-SMEM Rt, FFMA2,
// st.async + mbarrier partial exchange). No changes.
// smem (floats): Rt G*PAD=52224 | Hs 128 | Ps 2*1536 | mbar
// ---------------------------------------------------------------------------
#define RT_FLOATS   (G * PAD)                 /* 52224 */
#define HS_OFF      RT_FLOATS
#define PS_OFF      (HS_OFF + NB * KS)        /* 52352 */
#define PBUF_FLOATS (CLU * NB * 3 * KS)       /* 1536  */
#define MB_OFF      (PS_OFF + 2 * PBUF_FLOATS)/* 55424 */
#define SMEM_BYTES  (MB_OFF * 4 + 16)         /* 221712 */
#define RX_BYTES    (CLU * KS * 6 * 4)        /* 6144 per step */

__global__ void __launch_bounds__(TPB, 1) __cluster_dims__(CLU, 1, 1)
scan_kernel(const float* __restrict__ R, float* __restrict__ out)
{
    extern __shared__ float smem[];
    float* Rt = smem;
    float* Hs = smem + HS_OFF;
    float* Ps = smem + PS_OFF;

    const int      tid  = threadIdx.x;
    const uint32_t rank = ctarank();
    const int      cl   = blockIdx.x / CLU;
    const int      b0g  = cl * NB;

    const uint32_t mb_local = smem_u32(smem + MB_OFF);
    if (tid == 0) {
        mbar_init(mb_local,     1);
        mbar_init(mb_local + 8, 1);
    }

    // load own 64-row slice of R, transposed: Rt[g*PAD + k]
    {
        const float* src = R + (size_t)rank * KS * G;
        for (int i = tid; i < KS * G; i += TPB) {
            const int k = i / G;
            const int g = i - k * G;
            Rt[g * PAD + k] = src[i];
        }
    }
    if (tid < NB * KS) Hs[tid] = 0.0f;
    __syncthreads();
    cluster_sync();   // barriers + Rt visible cluster-wide before any st.async

    // gemv-thread constants: thread j owns gate columns j, H+j, 2H+j
    const int j       = tid;
    const int dstRank = j >> 6;
    const int u64     = j & 63;
    const uint32_t ps_local  = smem_u32(Ps);
    const uint32_t slot_off  = (uint32_t)(((rank * NB) * 3) * KS + u64) * 4u;
    const uint32_t rem_base0 = mapa_cluster(ps_local + slot_off, (uint32_t)dstRank);
    const uint32_t rem_mb    = mapa_cluster(mb_local, (uint32_t)dstRank);
    const uint32_t BUF_B  = (uint32_t)PBUF_FLOATS * 4u;  // 6144
    const uint32_t BAT_B  = (uint32_t)(3 * KS) * 4u;     // 768
    const uint32_t GATE_B = (uint32_t)KS * 4u;           // 256

    const uint32_t wz_a = smem_u32(Rt) + (uint32_t)j * (PAD * 4u);
    const uint32_t wr_a = wz_a + (uint32_t)H * (PAD * 4u);
    const uint32_t wh_a = wr_a + (uint32_t)H * (PAD * 4u);
    const uint32_t h0_a = smem_u32(Hs);
    const uint32_t h1_a = h0_a + KS * 4u;

    // gate-thread constants (tid < 128)
    const int gb  = tid >> 6;
    const int gu  = tid & 63;
    const int guu = (int)rank * KS + gu;
    const float* xp_gate  = g_xproj + ((size_t)(b0g + gb) * T) * G + guu;
    float*       out_gate = out     + ((size_t)(b0g + gb) * T) * H + guu;

    for (int t = 0; t < T; t++) {
        const int      bi  = t & 1;
        const uint32_t par = (uint32_t)((t >> 1) & 1);

        if (tid == 0) mbar_expect_tx(mb_local + bi * 8, RX_BYTES);

        // prefetch xproj gate inputs (hide GMEM latency under gemv)
        float xz = 0.f, xr = 0.f, xh = 0.f;
        if (tid < NB * KS) {
            const float* xp = xp_gate + (size_t)t * G;
            xz = __ldg(xp); xr = __ldg(xp + H); xh = __ldg(xp + 2 * H);
        }

        // partial GEMV over own k-slice: packed f32x2 FFMA (FFMA2)
        ull a00 = 0ULL, a01 = 0ULL, a02 = 0ULL;
        ull a10 = 0ULL, a11 = 0ULL, a12 = 0ULL;
#pragma unroll
        for (int k4 = 0; k4 < KS / 4; k4++) {
            const uint32_t o = (uint32_t)k4 * 16u;
            ull wa0, wa1, wb0, wb1, wc0, wc1, p0, p1, q0, q1;
            lds_v2b64(wa0, wa1, wz_a + o);
            lds_v2b64(wb0, wb1, wr_a + o);
            lds_v2b64(wc0, wc1, wh_a + o);
            lds_v2b64(p0,  p1,  h0_a + o);
            lds_v2b64(q0,  q1,  h1_a + o);
            a00 = ffma2(p0, wa0, a00);  a00 = ffma2(p1, wa1, a00);
            a01 = ffma2(p0, wb0, a01);  a01 = ffma2(p1, wb1, a01);
            a02 = ffma2(p0, wc0, a02);  a02 = ffma2(p1, wc1, a02);
            a10 = ffma2(q0, wa0, a10);  a10 = ffma2(q1, wa1, a10);
            a11 = ffma2(q0, wb0, a11);  a11 = ffma2(q1, wb1, a11);
            a12 = ffma2(q0, wc0, a12);  a12 = ffma2(q1, wc1, a12);
        }

        // scatter partials to owner CTA; each store counts tx on owner's barrier
        {
            const uint32_t base = rem_base0 + (uint32_t)bi * BUF_B;
            const uint32_t mbr  = rem_mb + (uint32_t)bi * 8u;
            st_async_f32(base,                       red2(a00), mbr);
            st_async_f32(base + GATE_B,              red2(a01), mbr);
            st_async_f32(base + 2u * GATE_B,         red2(a02), mbr);
            st_async_f32(base + BAT_B,               red2(a10), mbr);
            st_async_f32(base + BAT_B + GATE_B,      red2(a11), mbr);
            st_async_f32(base + BAT_B + 2u * GATE_B, red2(a12), mbr);
        }

        // gates: wait for all partials, then update own 64 units x 2 batches
        if (tid < NB * KS) {
            mbar_wait(mb_local + bi * 8, par);
            const float* pb = Ps + bi * PBUF_FLOATS;
            float sz = 0.f, sr = 0.f, sh = 0.f;
#pragma unroll
            for (int s = 0; s < CLU; s++) {
                const float* qq = pb + (s * NB + gb) * (3 * KS) + gu;
                sz += qq[0]; sr += qq[KS]; sh += qq[2 * KS];
            }
            const float z  = sigmoid_f(xz + sz);
            const float r  = sigmoid_f(xr + sr);
            const float hh = tanh_f(xh + r * sh);
            const float hn = z * Hs[tid] + (1.0f - z) * hh;
            Hs[tid] = hn;
            out_gate[(size_t)t * H] = hn;
        }
        __syncthreads();   // Hs update visible before next gemv
    }

    cluster_sync();   // keep CTAs alive until all peer traffic drained
}

// ---------------------------------------------------------------------------
// Kernel C: state = tanh(h_last @ dense_w + dense_b)
// ---------------------------------------------------------------------------
__global__ void __launch_bounds__(D) dense_kernel(
    const float* __restrict__ out, const float* __restrict__ w,
    const float* __restrict__ bias, float* __restrict__ state)
{
    const int b = blockIdx.x;
    const int d = threadIdx.x;
    const float* hl = out + ((size_t)b * T + (T - 1)) * H;
    float acc = bias[d];
#pragma unroll 4
    for (int k = 0; k < H; k++)
        acc += hl[k] * w[k * D + d];
    state[(size_t)b * D + d] = tanhf(acc);
}

// ---------------------------------------------------------------------------
extern "C" void kernel_launch(void* const* d_in, const int* in_sizes, int n_in,
                              void* d_out, int out_size)
{
    const float* x     = (const float*)d_in[0];
    const float* kern  = (const float*)d_in[1];
    const float* rkern = (const float*)d_in[2];
    const float* bias  = (const float*)d_in[3];
    const float* dw    = (const float*)d_in[4];
    const float* db    = (const float*)d_in[5];

    float* out   = (float*)d_out;
    float* state = out + (size_t)B * T * H;

    cudaFuncSetAttribute(scan_kernel,
                         cudaFuncAttributeMaxDynamicSharedMemorySize, SMEM_BYTES);

    xproj_kernel<<<(B * T) / XP_ROWS, XP_TPB>>>(x, kern, bias);
    scan_kernel<<<(B / NB) * CLU, TPB, SMEM_BYTES>>>(rkern, out);
    dense_kernel<<<B, D>>>(out, dw, db, state);
}